// round 3
// baseline (speedup 1.0000x reference)
#include <cuda_runtime.h>
#include <math.h>

#define EPSJ 1e-6f
#define NB   2000
#define DIM  4000
#define DIMP 4096
#define NE   6000
#define LDA  4128
#define NTHREADS 256

__device__ float d_J[(size_t)DIMP * LDA];
__device__ float d_x[DIMP];
__device__ float d_y[DIMP];
__device__ float d_Pacc[NB];
__device__ float d_Qacc[NB];
__device__ float d_kp[NB];
__device__ float d_kq[NB];
__device__ volatile unsigned d_bar_gen;
__device__ unsigned d_bar_cnt;

struct Params {
    const float* x_in; const int* ei;
    const float *br_r, *br_x, *g_fr, *b_fr, *g_to, *b_to, *tap, *shift;
    const float *p_spec, *q_spec, *gs, *bs;
    const int* bt; const float* vmset;
    float* out;
};

union Shared {
    struct { float s[64][65]; } diag;
    struct { float su[64][65]; float sa[64][65]; float sinv[64]; } trsm;
    struct { float As[16][132]; float Bs[16][132]; } gemm;
    struct { float m[64][65]; float y[64]; } sub;
};

/* ---- software grid barrier (grid sized for guaranteed co-residency) ---- */
__device__ __forceinline__ void gsync()
{
    __syncthreads();
    if (threadIdx.x == 0) {
        __threadfence();
        unsigned gen = d_bar_gen;
        if (atomicAdd(&d_bar_cnt, 1u) == gridDim.x - 1) {
            d_bar_cnt = 0;
            __threadfence();
            d_bar_gen = gen + 1;
        } else {
            while (d_bar_gen == gen) __nanosleep(64);
            __threadfence();
        }
    }
    __syncthreads();
}

/* ---- LU 64x64 diagonal factor (no pivot), one block ---- */
__device__ void lu_diag(int k, Shared* sh)
{
    float (*s)[65] = sh->diag.s;
    int tid = threadIdx.x;
    __syncthreads();
    for (int idx = tid; idx < 4096; idx += NTHREADS)
        s[idx >> 6][idx & 63] = d_J[(size_t)(k + (idx >> 6)) * LDA + k + (idx & 63)];
    __syncthreads();
    int i = tid & 63, cgp = tid >> 6;
    for (int j = 0; j < 64; j++) {
        float lij = (i > j) ? s[i][j] * (1.f / s[j][j]) : 0.f;
        if (i > j)
            for (int c = cgp; c < 64; c += 4)
                if (c > j) s[i][c] -= lij * s[j][c];
        __syncthreads();
    }
    for (int idx = tid; idx < 4096; idx += NTHREADS) {
        int r = idx >> 6, c = idx & 63;
        float v = s[r][c];
        if (r > c) v *= (1.f / s[c][c]);
        d_J[(size_t)(k + r) * LDA + k + c] = v;
    }
}

/* ---- L21 tile = A21 * U11^{-1} ---- */
__device__ void trsm_row(int k, int r0, Shared* sh)
{
    float (*su)[65] = sh->trsm.su;
    float (*sa)[65] = sh->trsm.sa;
    float* sinv = sh->trsm.sinv;
    int tid = threadIdx.x;
    __syncthreads();
    for (int idx = tid; idx < 4096; idx += NTHREADS) {
        int i = idx >> 6, j = idx & 63;
        su[i][j] = d_J[(size_t)(k + i) * LDA + k + j];
        sa[i][j] = d_J[(size_t)(r0 + i) * LDA + k + j];
    }
    __syncthreads();
    if (tid < 64) sinv[tid] = 1.f / su[tid][tid];
    __syncthreads();
    for (int idx = tid; idx < 4096; idx += NTHREADS)
        su[idx >> 6][idx & 63] *= sinv[idx >> 6];
    __syncthreads();
    int i = tid & 63, cgp = tid >> 6;
    for (int j = 0; j < 64; j++) {
        float aij = sa[i][j];
        for (int c = cgp; c < 64; c += 4)
            if (c > j) sa[i][c] -= aij * su[j][c];
        __syncthreads();
    }
    for (int idx = tid; idx < 4096; idx += NTHREADS) {
        int r = idx >> 6, j = idx & 63;
        d_J[(size_t)(r0 + r) * LDA + k + j] = sa[r][j] * sinv[j];
    }
}

/* ---- U12 tile = L11^{-1} * A12 ---- */
__device__ void trsm_col(int k, int c0, Shared* sh)
{
    float (*sl)[65] = sh->trsm.su;
    float (*sa)[65] = sh->trsm.sa;
    int tid = threadIdx.x;
    __syncthreads();
    for (int idx = tid; idx < 4096; idx += NTHREADS) {
        int i = idx >> 6, j = idx & 63;
        sl[i][j] = d_J[(size_t)(k + i) * LDA + k + j];
        sa[i][j] = d_J[(size_t)(k + i) * LDA + c0 + j];
    }
    __syncthreads();
    int c = tid & 63, rg = tid >> 6;
    for (int j = 0; j < 64; j++) {
        float ajc = sa[j][c];
        for (int i2 = rg; i2 < 64; i2 += 4)
            if (i2 > j) sa[i2][c] -= sl[i2][j] * ajc;
        __syncthreads();
    }
    for (int idx = tid; idx < 4096; idx += NTHREADS)
        d_J[(size_t)(k + (idx >> 6)) * LDA + c0 + (idx & 63)] = sa[idx >> 6][idx & 63];
}

/* ---- trailing update: one 128x128 tile, K=64 ---- */
__device__ void gemm_tile(int k, int m, int row0, int col0, Shared* sh)
{
    const int k2 = k + 64;
    float (*As)[132] = sh->gemm.As;
    float (*Bs)[132] = sh->gemm.Bs;
    const int tid = threadIdx.x;
    const int ty = tid >> 4, tx = tid & 15;
    float acc[8][8];
#pragma unroll
    for (int u = 0; u < 8; u++)
#pragma unroll
        for (int v = 0; v < 8; v++) acc[u][v] = 0.f;

    __syncthreads();
    for (int kk0 = 0; kk0 < 64; kk0 += 16) {
#pragma unroll
        for (int sld = 0; sld < 2; sld++) {
            int t2 = tid + sld * NTHREADS;
            int i = t2 >> 2, j4 = (t2 & 3) << 2;
            float4 v = make_float4(0.f, 0.f, 0.f, 0.f);
            if (row0 + i < m)
                v = *(const float4*)&d_J[(size_t)(k2 + row0 + i) * LDA + (k + kk0 + j4)];
            As[j4 + 0][i] = v.x; As[j4 + 1][i] = v.y;
            As[j4 + 2][i] = v.z; As[j4 + 3][i] = v.w;
        }
#pragma unroll
        for (int sld = 0; sld < 2; sld++) {
            int t2 = tid + sld * NTHREADS;
            int kk = t2 >> 5, c4 = (t2 & 31) << 2;
            float4 v = make_float4(0.f, 0.f, 0.f, 0.f);
            if (col0 + c4 < m)
                v = *(const float4*)&d_J[(size_t)(k + kk0 + kk) * LDA + (k2 + col0 + c4)];
            Bs[kk][c4 + 0] = v.x; Bs[kk][c4 + 1] = v.y;
            Bs[kk][c4 + 2] = v.z; Bs[kk][c4 + 3] = v.w;
        }
        __syncthreads();
#pragma unroll
        for (int kk = 0; kk < 16; kk++) {
            float a[8], b[8];
#pragma unroll
            for (int u = 0; u < 8; u++) a[u] = As[kk][ty * 8 + u];
#pragma unroll
            for (int v = 0; v < 8; v++) b[v] = Bs[kk][tx * 8 + v];
#pragma unroll
            for (int u = 0; u < 8; u++)
#pragma unroll
                for (int v = 0; v < 8; v++) acc[u][v] += a[u] * b[v];
        }
        __syncthreads();
    }
#pragma unroll
    for (int u = 0; u < 8; u++) {
        int i = row0 + ty * 8 + u;
        if (i < m) {
            size_t base = (size_t)(k2 + i) * LDA + k2;
#pragma unroll
            for (int v = 0; v < 8; v++) {
                int c = col0 + tx * 8 + v;
                if (c < m) d_J[base + c] -= acc[u][v];
            }
        }
    }
}

/* ---- substitution diagonal solves (one block) ---- */
__device__ void subst_diag_fwd(int k, Shared* sh)
{
    int t = threadIdx.x;
    __syncthreads();
    for (int idx = t; idx < 4096; idx += NTHREADS)
        sh->sub.m[idx >> 6][idx & 63] = d_J[(size_t)(k + (idx >> 6)) * LDA + k + (idx & 63)];
    if (t < 64) sh->sub.y[t] = d_y[k + t];
    __syncthreads();
    for (int j = 0; j < 63; j++) {
        if (t > j && t < 64) sh->sub.y[t] -= sh->sub.m[t][j] * sh->sub.y[j];
        __syncthreads();
    }
    if (t < 64) d_y[k + t] = sh->sub.y[t];
}

__device__ void subst_diag_bwd(int k, Shared* sh)
{
    int t = threadIdx.x;
    __syncthreads();
    for (int idx = t; idx < 4096; idx += NTHREADS)
        sh->sub.m[idx >> 6][idx & 63] = d_J[(size_t)(k + (idx >> 6)) * LDA + k + (idx & 63)];
    if (t < 64) sh->sub.y[t] = d_y[k + t];
    __syncthreads();
    for (int j = 63; j >= 0; j--) {
        if (t == j) sh->sub.y[j] *= (1.f / sh->sub.m[j][j]);
        __syncthreads();
        if (t < j) sh->sub.y[t] -= sh->sub.m[t][j] * sh->sub.y[j];
        __syncthreads();
    }
    if (t < 64) d_y[k + t] = sh->sub.y[t];
}

/* =======================================================================
 *  The one persistent kernel
 * ======================================================================= */
__global__ void __launch_bounds__(NTHREADS, 1) solver_kernel(Params P)
{
    __shared__ Shared sh;
    const int tid = threadIdx.x;
    const int gsize = gridDim.x * NTHREADS;
    const int gtid = blockIdx.x * NTHREADS + tid;
    const int warps_total = gridDim.x * (NTHREADS / 32);
    const int warp = tid >> 5, lane = tid & 31;
    const int gwarp = blockIdx.x * (NTHREADS / 32) + warp;

    /* init state + masks */
    for (int i = gtid; i < DIMP; i += gsize) {
        d_x[i] = (i < DIM) ? P.x_in[i] : 0.0f;
        if (i < NB) {
            int b = P.bt[i];
            d_kp[i] = (b == 3) ? 0.f : 1.f;
            d_kq[i] = (b >= 2) ? 0.f : 1.f;
        }
    }
    gsync();

    for (int t5 = 0; t5 < 5; t5++) {
        /* ---- zero J + accumulators ---- */
        {
            size_t tot = (size_t)DIMP * LDA / 4;
            float4 z = make_float4(0.f, 0.f, 0.f, 0.f);
            for (size_t i = gtid; i < tot; i += gsize) ((float4*)d_J)[i] = z;
            for (int i = gtid; i < NB; i += gsize) { d_Pacc[i] = 0.f; d_Qacc[i] = 0.f; }
        }
        gsync();

        /* ---- edge assembly (atomics) ---- */
        for (int e = gtid; e < NE; e += gsize) {
            int s = P.ei[e], d = P.ei[NE + e];
            float vm_s = d_x[NB + s], vm_d = d_x[NB + d];
            float r = P.br_r[e], xx = P.br_x[e];
            float den = r * r + xx * xx;
            float g = r / den, b = -xx / den;
            float tp = P.tap[e];
            float th = d_x[s] - d_x[d];
            float sf, cf;
            sincosf(th - P.shift[e], &sf, &cf);
            float ct = cf, st = -sf;
            float vi_t = vm_s / tp;
            float vij = vm_s * vm_d / tp;

            float gfr = P.g_fr[e], bfr = P.b_fr[e], gto = P.g_to[e], bto = P.b_to[e];
            float Pf = vi_t * vi_t * (g + gfr) + vij * (-g * cf - b * sf);
            float Qf = -vi_t * vi_t * (b + bfr) + vij * (-g * sf + b * cf);
            float Pt = vm_d * vm_d * (g + gto) + vij * (-g * ct - b * st);
            float Qt = -vm_d * vm_d * (b + bto) + vij * (-g * st + b * ct);
            atomicAdd(&d_Pacc[s], Pf); atomicAdd(&d_Pacc[d], Pt);
            atomicAdd(&d_Qacc[s], Qf); atomicAdd(&d_Qacc[d], Qt);

            float Af = g * cf + b * sf, Bf = g * sf - b * cf;
            float At = g * ct + b * st, Bt = g * st - b * ct;
            size_t Rs  = (size_t)s * LDA, Rd = (size_t)d * LDA;
            size_t Rqs = (size_t)(NB + s) * LDA, Rqd = (size_t)(NB + d) * LDA;

            if (d_kp[s] != 0.f) {
                atomicAdd(&d_J[Rs + s],      -vij * Bf);
                atomicAdd(&d_J[Rs + d],       vij * Bf);
                atomicAdd(&d_J[Rs + NB + s], -(2.f * vm_s / (tp * tp) * (g + gfr) - vm_d / tp * Af));
                atomicAdd(&d_J[Rs + NB + d],  (vm_s / tp) * Af);
            }
            if (d_kp[d] != 0.f) {
                atomicAdd(&d_J[Rd + d],      -vij * Bt);
                atomicAdd(&d_J[Rd + s],       vij * Bt);
                atomicAdd(&d_J[Rd + NB + d], -(2.f * vm_d * (g + gto) - vm_s / tp * At));
                atomicAdd(&d_J[Rd + NB + s],  (vm_d / tp) * At);
            }
            if (d_kq[s] != 0.f) {
                atomicAdd(&d_J[Rqs + s],      vij * Af);
                atomicAdd(&d_J[Rqs + d],     -vij * Af);
                atomicAdd(&d_J[Rqs + NB + s], (2.f * vm_s / (tp * tp) * (b + bfr) + vm_d / tp * Bf));
                atomicAdd(&d_J[Rqs + NB + d], (vm_s / tp) * Bf);
            }
            if (d_kq[d] != 0.f) {
                atomicAdd(&d_J[Rqd + d],      vij * At);
                atomicAdd(&d_J[Rqd + s],     -vij * At);
                atomicAdd(&d_J[Rqd + NB + d], (2.f * vm_d * (b + bto) + vm_s / tp * Bt));
                atomicAdd(&d_J[Rqd + NB + s], (vm_s / tp) * Bt);
            }
        }
        gsync();

        /* ---- diagonal terms + RHS ---- */
        for (int i = gtid; i < DIMP; i += gsize) {
            if (i < NB) {
                int b = P.bt[i];
                float vm = d_x[NB + i];
                d_J[(size_t)i * LDA + i]               += ((b == 3) ? 1.f : 0.f) + EPSJ;
                d_J[(size_t)i * LDA + NB + i]          += d_kp[i] * (-2.f * vm * P.gs[i]);
                d_J[(size_t)(NB + i) * LDA + (NB + i)] += d_kq[i] * (2.f * vm * P.bs[i]) + ((b >= 2) ? 1.f : 0.f) + EPSJ;
                d_y[i] = (b == 3) ? d_x[i] : (P.p_spec[i] - (d_Pacc[i] + vm * vm * P.gs[i]));
            } else if (i < DIM) {
                int ib = i - NB;
                float vm = d_x[i];
                d_y[i] = (P.bt[ib] >= 2) ? (vm - P.vmset[ib])
                                         : (P.q_spec[ib] - (d_Qacc[ib] - vm * vm * P.bs[ib]));
            } else {
                d_J[(size_t)i * LDA + i] = 1.0f;
                d_y[i] = 0.f;
            }
        }
        gsync();

        /* ---- blocked LU (no pivot) ---- */
        for (int k = 0; k < DIMP; k += 64) {
            if (blockIdx.x == 0) lu_diag(k, &sh);
            gsync();
            int m = DIMP - k - 64;
            if (m > 0) {
                int ntr = m / 64;
                for (int job = blockIdx.x; job < 2 * ntr; job += gridDim.x) {
                    if (job < ntr) trsm_row(k, k + 64 + job * 64, &sh);
                    else           trsm_col(k, k + 64 + (job - ntr) * 64, &sh);
                }
            }
            gsync();
            if (m > 0) {
                int g = (m + 127) / 128;
                for (int job = blockIdx.x; job < g * g; job += gridDim.x)
                    gemm_tile(k, m, (job / g) * 128, (job % g) * 128, &sh);
            }
            gsync();
        }

        /* ---- forward substitution ---- */
        for (int k = 0; k < DIMP; k += 64) {
            if (blockIdx.x == 0) subst_diag_fwd(k, &sh);
            gsync();
            if (k + 64 < DIMP) {
                __syncthreads();
                if (tid < 64) sh.sub.y[tid] = d_y[k + tid];
                __syncthreads();
                for (int r = k + 64 + gwarp; r < DIMP; r += warps_total) {
                    const float* row = &d_J[(size_t)r * LDA + k];
                    float s = row[lane] * sh.sub.y[lane] + row[lane + 32] * sh.sub.y[lane + 32];
#pragma unroll
                    for (int o = 16; o; o >>= 1) s += __shfl_down_sync(0xffffffffu, s, o);
                    if (lane == 0) d_y[r] -= s;
                }
            }
            gsync();
        }

        /* ---- backward substitution ---- */
        for (int k = DIMP - 64; k >= 0; k -= 64) {
            if (blockIdx.x == 0) subst_diag_bwd(k, &sh);
            gsync();
            if (k > 0) {
                __syncthreads();
                if (tid < 64) sh.sub.y[tid] = d_y[k + tid];
                __syncthreads();
                for (int r = gwarp; r < k; r += warps_total) {
                    const float* row = &d_J[(size_t)r * LDA + k];
                    float s = row[lane] * sh.sub.y[lane] + row[lane + 32] * sh.sub.y[lane + 32];
#pragma unroll
                    for (int o = 16; o; o >>= 1) s += __shfl_down_sync(0xffffffffu, s, o);
                    if (lane == 0) d_y[r] -= s;
                }
            }
            gsync();
        }

        /* ---- Newton update ---- */
        for (int i = gtid; i < DIM; i += gsize) {
            float v = d_x[i] - d_y[i];
            if (i >= NB) v = fminf(fmaxf(v, 0.5f), 1.5f);
            d_x[i] = v;
        }
        gsync();
    }

    for (int i = gtid; i < DIM; i += gsize)
        P.out[i] = d_x[i];
}

extern "C" void kernel_launch(void* const* d_in, const int* in_sizes, int n_in,
                              void* d_out, int out_size)
{
    Params P;
    P.x_in   = (const float*)d_in[0];
    P.ei     = (const int*)  d_in[1];
    P.br_r   = (const float*)d_in[2];
    P.br_x   = (const float*)d_in[3];
    P.g_fr   = (const float*)d_in[4];
    P.b_fr   = (const float*)d_in[5];
    P.g_to   = (const float*)d_in[6];
    P.b_to   = (const float*)d_in[7];
    P.tap    = (const float*)d_in[8];
    P.shift  = (const float*)d_in[9];
    P.p_spec = (const float*)d_in[10];
    P.q_spec = (const float*)d_in[11];
    P.gs     = (const float*)d_in[12];
    P.bs     = (const float*)d_in[13];
    P.bt     = (const int*)  d_in[14];
    P.vmset  = (const float*)d_in[15];
    P.out    = (float*)d_out;

    int dev = 0, nsm = 0, per_sm = 0;
    cudaGetDevice(&dev);
    cudaDeviceGetAttribute(&nsm, cudaDevAttrMultiProcessorCount, dev);
    cudaOccupancyMaxActiveBlocksPerMultiprocessor(&per_sm, solver_kernel, NTHREADS, 0);
    if (per_sm < 1) per_sm = 1;
    int grid = nsm * per_sm;
    if (grid < 1) grid = 1;
    if (grid > 1024) grid = 1024;

    solver_kernel<<<grid, NTHREADS>>>(P);
}

// round 4
// speedup vs baseline: 1.7694x; 1.7694x over previous
#include <cuda_runtime.h>
#include <math.h>

#define EPSJ 1e-6f
#define NB   2000
#define DIM  4000
#define DIMP 4096
#define NE   6000
#define LDA  4128
#define NTHREADS 512
#define NWARPS   (NTHREADS / 32)

__device__ float d_J[(size_t)DIMP * LDA];
__device__ float d_x[DIMP];
__device__ float d_y[DIMP];
__device__ float d_Pacc[NB];
__device__ float d_Qacc[NB];
__device__ float d_kp[NB];
__device__ float d_kq[NB];
__device__ volatile unsigned d_bar_gen;
__device__ unsigned d_bar_cnt;

struct Params {
    const float* x_in; const int* ei;
    const float *br_r, *br_x, *g_fr, *b_fr, *g_to, *b_to, *tap, *shift;
    const float *p_spec, *q_spec, *gs, *bs;
    const int* bt; const float* vmset;
    float* out;
};

union Shared {
    struct { float s[64][65]; } diag;
    struct { float su[64][65]; float sa[64][65]; float sinv[64]; } trsm;
    struct { float As[2][16][132]; float Bs[2][16][132]; } gemm;
    struct { float m[64][65]; float y[64]; float yc[64]; } sub;
};

/* ---------- f32x2 packed-FMA helpers ---------- */
__device__ __forceinline__ unsigned long long pk2(float x)
{
    unsigned long long r;
    asm("mov.b64 %0, {%1, %1};" : "=l"(r) : "f"(x));
    return r;
}
__device__ __forceinline__ void fma2(unsigned long long& d,
                                     unsigned long long a, unsigned long long b)
{
    asm("fma.rn.f32x2 %0, %1, %2, %0;" : "+l"(d) : "l"(a), "l"(b));
}
__device__ __forceinline__ float2 upk(unsigned long long v)
{
    float lo, hi;
    asm("mov.b64 {%0, %1}, %2;" : "=f"(lo), "=f"(hi) : "l"(v));
    return make_float2(lo, hi);
}

/* ---------- software grid barrier ---------- */
__device__ __forceinline__ void gsync()
{
    __syncthreads();
    if (threadIdx.x == 0) {
        __threadfence();
        unsigned gen = d_bar_gen;
        if (atomicAdd(&d_bar_cnt, 1u) == gridDim.x - 1) {
            d_bar_cnt = 0;
            __threadfence();
            d_bar_gen = gen + 1;
        } else {
            while (d_bar_gen == gen) { }
            __threadfence();
        }
    }
    __syncthreads();
}

/* ---------- LU 64x64 diagonal factor (no pivot), one block ---------- */
__device__ void lu_diag(int k, Shared* sh)
{
    float (*s)[65] = sh->diag.s;
    int tid = threadIdx.x;
    __syncthreads();
    for (int idx = tid; idx < 4096; idx += NTHREADS)
        s[idx >> 6][idx & 63] = d_J[(size_t)(k + (idx >> 6)) * LDA + k + (idx & 63)];
    __syncthreads();
    int i = tid & 63, cgp = tid >> 6;
    for (int j = 0; j < 64; j++) {
        float lij = (i > j) ? s[i][j] * (1.f / s[j][j]) : 0.f;
        if (i > j)
            for (int c = cgp; c < 64; c += NTHREADS / 64)
                if (c > j) s[i][c] -= lij * s[j][c];
        __syncthreads();
    }
    for (int idx = tid; idx < 4096; idx += NTHREADS) {
        int r = idx >> 6, c = idx & 63;
        float v = s[r][c];
        if (r > c) v *= (1.f / s[c][c]);
        d_J[(size_t)(k + r) * LDA + k + c] = v;
    }
}

/* ---------- L21 tile = A21 * U11^{-1} ---------- */
__device__ void trsm_row(int k, int r0, Shared* sh)
{
    float (*su)[65] = sh->trsm.su;
    float (*sa)[65] = sh->trsm.sa;
    float* sinv = sh->trsm.sinv;
    int tid = threadIdx.x;
    __syncthreads();
    for (int idx = tid; idx < 4096; idx += NTHREADS) {
        int i = idx >> 6, j = idx & 63;
        su[i][j] = d_J[(size_t)(k + i) * LDA + k + j];
        sa[i][j] = d_J[(size_t)(r0 + i) * LDA + k + j];
    }
    __syncthreads();
    if (tid < 64) sinv[tid] = 1.f / su[tid][tid];
    __syncthreads();
    for (int idx = tid; idx < 4096; idx += NTHREADS)
        su[idx >> 6][idx & 63] *= sinv[idx >> 6];
    __syncthreads();
    int i = tid & 63, cgp = tid >> 6;
    for (int j = 0; j < 64; j++) {
        float aij = sa[i][j];
        for (int c = cgp; c < 64; c += NTHREADS / 64)
            if (c > j) sa[i][c] -= aij * su[j][c];
        __syncthreads();
    }
    for (int idx = tid; idx < 4096; idx += NTHREADS) {
        int r = idx >> 6, j = idx & 63;
        d_J[(size_t)(r0 + r) * LDA + k + j] = sa[r][j] * sinv[j];
    }
}

/* ---------- U12 tile = L11^{-1} * A12 ---------- */
__device__ void trsm_col(int k, int c0, Shared* sh)
{
    float (*sl)[65] = sh->trsm.su;
    float (*sa)[65] = sh->trsm.sa;
    int tid = threadIdx.x;
    __syncthreads();
    for (int idx = tid; idx < 4096; idx += NTHREADS) {
        int i = idx >> 6, j = idx & 63;
        sl[i][j] = d_J[(size_t)(k + i) * LDA + k + j];
        sa[i][j] = d_J[(size_t)(k + i) * LDA + c0 + j];
    }
    __syncthreads();
    int c = tid & 63, rg = tid >> 6;
    for (int j = 0; j < 64; j++) {
        float ajc = sa[j][c];
        for (int i2 = rg; i2 < 64; i2 += NTHREADS / 64)
            if (i2 > j) sa[i2][c] -= sl[i2][j] * ajc;
        __syncthreads();
    }
    for (int idx = tid; idx < 4096; idx += NTHREADS)
        d_J[(size_t)(k + (idx >> 6)) * LDA + c0 + (idx & 63)] = sa[idx >> 6][idx & 63];
}

/* ---------- trailing update tile: 128x128, K=64, f32x2, double-buffered ---------- */
__device__ void gemm_tile(int k, int m, int row0, int col0, Shared* sh)
{
    const int k2 = k + 64;
    const int tid = threadIdx.x;
    const int ty = tid >> 5;            /* 0..15 : 8 rows each   */
    const int tx = tid & 31;            /* 0..31 : 4 cols each   */
    const int ai = tid >> 2;            /* 0..127 A-row loader   */
    const int aj = (tid & 3) << 2;      /* 0,4,8,12              */
    const int bk = tid >> 5;            /* 0..15  B-k loader     */
    const int bc = (tid & 31) << 2;     /* 0..124                */
    const bool arow_ok = (row0 + ai) < m;
    const bool bcol_ok = (col0 + bc) < m;
    const float* gA = &d_J[(size_t)(k2 + row0 + ai) * LDA + k + aj];
    const float* gB = &d_J[(size_t)(k + bk) * LDA + k2 + col0 + bc];

    unsigned long long acc[4][4];
#pragma unroll
    for (int u = 0; u < 4; u++)
#pragma unroll
        for (int v = 0; v < 4; v++) acc[u][v] = 0ull;

    float4 z4 = make_float4(0.f, 0.f, 0.f, 0.f);
    float4 ra = arow_ok ? *(const float4*)gA : z4;
    float4 rb = bcol_ok ? *(const float4*)gB : z4;

    __syncthreads();                     /* union reuse guard */
    sh->gemm.As[0][aj + 0][ai] = ra.x;
    sh->gemm.As[0][aj + 1][ai] = ra.y;
    sh->gemm.As[0][aj + 2][ai] = ra.z;
    sh->gemm.As[0][aj + 3][ai] = ra.w;
    *(float4*)&sh->gemm.Bs[0][bk][bc] = rb;
    __syncthreads();

    for (int c = 0; c < 4; c++) {
        const int cur = c & 1;
        float4 na, nb;
        if (c < 3) {
            na = arow_ok ? *(const float4*)(gA + (c + 1) * 16) : z4;
            nb = bcol_ok ? *(const float4*)(gB + (size_t)(c + 1) * 16 * LDA) : z4;
        }
#pragma unroll
        for (int kk = 0; kk < 16; kk++) {
            const unsigned long long* ap =
                (const unsigned long long*)&sh->gemm.As[cur][kk][ty * 8];
            unsigned long long a0 = ap[0], a1 = ap[1], a2 = ap[2], a3 = ap[3];
            float4 bv = *(const float4*)&sh->gemm.Bs[cur][kk][tx * 4];
            unsigned long long b0 = pk2(bv.x), b1 = pk2(bv.y),
                               b2 = pk2(bv.z), b3 = pk2(bv.w);
            fma2(acc[0][0], a0, b0); fma2(acc[0][1], a0, b1);
            fma2(acc[0][2], a0, b2); fma2(acc[0][3], a0, b3);
            fma2(acc[1][0], a1, b0); fma2(acc[1][1], a1, b1);
            fma2(acc[1][2], a1, b2); fma2(acc[1][3], a1, b3);
            fma2(acc[2][0], a2, b0); fma2(acc[2][1], a2, b1);
            fma2(acc[2][2], a2, b2); fma2(acc[2][3], a2, b3);
            fma2(acc[3][0], a3, b0); fma2(acc[3][1], a3, b1);
            fma2(acc[3][2], a3, b2); fma2(acc[3][3], a3, b3);
        }
        if (c < 3) {
            const int nxt = cur ^ 1;
            sh->gemm.As[nxt][aj + 0][ai] = na.x;
            sh->gemm.As[nxt][aj + 1][ai] = na.y;
            sh->gemm.As[nxt][aj + 2][ai] = na.z;
            sh->gemm.As[nxt][aj + 3][ai] = na.w;
            *(float4*)&sh->gemm.Bs[nxt][bk][bc] = nb;
        }
        __syncthreads();
    }

#pragma unroll
    for (int u = 0; u < 4; u++) {
        int r0 = row0 + ty * 8 + u * 2;
        if (r0 < m && (col0 + tx * 4) < m) {
            float2 p0 = upk(acc[u][0]), p1 = upk(acc[u][1]);
            float2 p2 = upk(acc[u][2]), p3 = upk(acc[u][3]);
            float4* c0 = (float4*)&d_J[(size_t)(k2 + r0) * LDA + k2 + col0 + tx * 4];
            float4 v0 = *c0;
            v0.x -= p0.x; v0.y -= p1.x; v0.z -= p2.x; v0.w -= p3.x;
            *c0 = v0;
            float4* c1 = (float4*)&d_J[(size_t)(k2 + r0 + 1) * LDA + k2 + col0 + tx * 4];
            float4 v1 = *c1;
            v1.x -= p0.y; v1.y -= p1.y; v1.z -= p2.y; v1.w -= p3.y;
            *c1 = v1;
        }
    }
}

/* ---------- substitution diagonal solves (one block) ---------- */
__device__ void subst_diag_fwd(int k, Shared* sh)
{
    int t = threadIdx.x;
    __syncthreads();
    for (int idx = t; idx < 4096; idx += NTHREADS)
        sh->sub.m[idx >> 6][idx & 63] = d_J[(size_t)(k + (idx >> 6)) * LDA + k + (idx & 63)];
    if (t < 64) sh->sub.y[t] = d_y[k + t];
    __syncthreads();
    for (int j = 0; j < 63; j++) {
        if (t > j && t < 64) sh->sub.y[t] -= sh->sub.m[t][j] * sh->sub.y[j];
        __syncthreads();
    }
    if (t < 64) d_y[k + t] = sh->sub.y[t];
    __syncthreads();
}

__device__ void subst_diag_bwd(int k, Shared* sh)
{
    int t = threadIdx.x;
    __syncthreads();
    for (int idx = t; idx < 4096; idx += NTHREADS)
        sh->sub.m[idx >> 6][idx & 63] = d_J[(size_t)(k + (idx >> 6)) * LDA + k + (idx & 63)];
    if (t < 64) sh->sub.y[t] = d_y[k + t];
    __syncthreads();
    for (int j = 63; j >= 0; j--) {
        if (t == j) sh->sub.y[j] *= (1.f / sh->sub.m[j][j]);
        __syncthreads();
        if (t < j) sh->sub.y[t] -= sh->sub.m[t][j] * sh->sub.y[j];
        __syncthreads();
    }
    if (t < 64) d_y[k + t] = sh->sub.y[t];
    __syncthreads();
}

/* ---------- row-update helper for substitution (one 64-dot per warp) ---------- */
__device__ __forceinline__ void subst_row_update(int r, int k, const float* yc, int lane)
{
    const float* row = &d_J[(size_t)r * LDA + k];
    float s = row[lane] * yc[lane] + row[lane + 32] * yc[lane + 32];
#pragma unroll
    for (int o = 16; o; o >>= 1) s += __shfl_down_sync(0xffffffffu, s, o);
    if (lane == 0) d_y[r] -= s;
}

/* =======================================================================
 *  The one persistent kernel
 * ======================================================================= */
__global__ void __launch_bounds__(NTHREADS, 1) solver_kernel(Params P)
{
    __shared__ Shared sh;
    const int tid = threadIdx.x;
    const int gsize = gridDim.x * NTHREADS;
    const int gtid = blockIdx.x * NTHREADS + tid;
    const int warp = tid >> 5, lane = tid & 31;

    for (int i = gtid; i < DIMP; i += gsize) {
        d_x[i] = (i < DIM) ? P.x_in[i] : 0.0f;
        if (i < NB) {
            int b = P.bt[i];
            d_kp[i] = (b == 3) ? 0.f : 1.f;
            d_kq[i] = (b >= 2) ? 0.f : 1.f;
        }
    }
    gsync();

    for (int t5 = 0; t5 < 5; t5++) {
        /* ---- zero J + accumulators ---- */
        {
            size_t tot = (size_t)DIMP * LDA / 4;
            float4 z = make_float4(0.f, 0.f, 0.f, 0.f);
            for (size_t i = gtid; i < tot; i += gsize) ((float4*)d_J)[i] = z;
            for (int i = gtid; i < NB; i += gsize) { d_Pacc[i] = 0.f; d_Qacc[i] = 0.f; }
        }
        gsync();

        /* ---- edge assembly ---- */
        for (int e = gtid; e < NE; e += gsize) {
            int s = P.ei[e], d = P.ei[NE + e];
            float vm_s = d_x[NB + s], vm_d = d_x[NB + d];
            float r = P.br_r[e], xx = P.br_x[e];
            float den = r * r + xx * xx;
            float g = r / den, b = -xx / den;
            float tp = P.tap[e];
            float th = d_x[s] - d_x[d];
            float sf, cf;
            sincosf(th - P.shift[e], &sf, &cf);
            float ct = cf, st = -sf;
            float vi_t = vm_s / tp;
            float vij = vm_s * vm_d / tp;

            float gfr = P.g_fr[e], bfr = P.b_fr[e], gto = P.g_to[e], bto = P.b_to[e];
            float Pf = vi_t * vi_t * (g + gfr) + vij * (-g * cf - b * sf);
            float Qf = -vi_t * vi_t * (b + bfr) + vij * (-g * sf + b * cf);
            float Pt = vm_d * vm_d * (g + gto) + vij * (-g * ct - b * st);
            float Qt = -vm_d * vm_d * (b + bto) + vij * (-g * st + b * ct);
            atomicAdd(&d_Pacc[s], Pf); atomicAdd(&d_Pacc[d], Pt);
            atomicAdd(&d_Qacc[s], Qf); atomicAdd(&d_Qacc[d], Qt);

            float Af = g * cf + b * sf, Bf = g * sf - b * cf;
            float At = g * ct + b * st, Bt = g * st - b * ct;
            size_t Rs  = (size_t)s * LDA, Rd = (size_t)d * LDA;
            size_t Rqs = (size_t)(NB + s) * LDA, Rqd = (size_t)(NB + d) * LDA;

            if (d_kp[s] != 0.f) {
                atomicAdd(&d_J[Rs + s],      -vij * Bf);
                atomicAdd(&d_J[Rs + d],       vij * Bf);
                atomicAdd(&d_J[Rs + NB + s], -(2.f * vm_s / (tp * tp) * (g + gfr) - vm_d / tp * Af));
                atomicAdd(&d_J[Rs + NB + d],  (vm_s / tp) * Af);
            }
            if (d_kp[d] != 0.f) {
                atomicAdd(&d_J[Rd + d],      -vij * Bt);
                atomicAdd(&d_J[Rd + s],       vij * Bt);
                atomicAdd(&d_J[Rd + NB + d], -(2.f * vm_d * (g + gto) - vm_s / tp * At));
                atomicAdd(&d_J[Rd + NB + s],  (vm_d / tp) * At);
            }
            if (d_kq[s] != 0.f) {
                atomicAdd(&d_J[Rqs + s],      vij * Af);
                atomicAdd(&d_J[Rqs + d],     -vij * Af);
                atomicAdd(&d_J[Rqs + NB + s], (2.f * vm_s / (tp * tp) * (b + bfr) + vm_d / tp * Bf));
                atomicAdd(&d_J[Rqs + NB + d], (vm_s / tp) * Bf);
            }
            if (d_kq[d] != 0.f) {
                atomicAdd(&d_J[Rqd + d],      vij * At);
                atomicAdd(&d_J[Rqd + s],     -vij * At);
                atomicAdd(&d_J[Rqd + NB + d], (2.f * vm_d * (b + bto) + vm_s / tp * Bt));
                atomicAdd(&d_J[Rqd + NB + s], (vm_s / tp) * Bt);
            }
        }
        gsync();

        /* ---- diagonal terms + RHS ---- */
        for (int i = gtid; i < DIMP; i += gsize) {
            if (i < NB) {
                int b = P.bt[i];
                float vm = d_x[NB + i];
                d_J[(size_t)i * LDA + i]               += ((b == 3) ? 1.f : 0.f) + EPSJ;
                d_J[(size_t)i * LDA + NB + i]          += d_kp[i] * (-2.f * vm * P.gs[i]);
                d_J[(size_t)(NB + i) * LDA + (NB + i)] += d_kq[i] * (2.f * vm * P.bs[i]) + ((b >= 2) ? 1.f : 0.f) + EPSJ;
                d_y[i] = (b == 3) ? d_x[i] : (P.p_spec[i] - (d_Pacc[i] + vm * vm * P.gs[i]));
            } else if (i < DIM) {
                int ib = i - NB;
                float vm = d_x[i];
                d_y[i] = (P.bt[ib] >= 2) ? (vm - P.vmset[ib])
                                         : (P.q_spec[ib] - (d_Qacc[ib] - vm * vm * P.bs[ib]));
            } else {
                d_J[(size_t)i * LDA + i] = 1.0f;
                d_y[i] = 0.f;
            }
        }
        gsync();

        /* ---- blocked LU with block-0 diag lookahead ---- */
        if (blockIdx.x == 0) lu_diag(0, &sh);
        gsync();
        for (int k = 0; k < DIMP - 64; k += 64) {
            int m = DIMP - k - 64;
            /* phase A: TRSM row+col tiles */
            {
                int ntr = m / 64;
                for (int job = blockIdx.x; job < 2 * ntr; job += gridDim.x) {
                    if (job < ntr) trsm_row(k, k + 64 + job * 64, &sh);
                    else           trsm_col(k, k + 64 + (job - ntr) * 64, &sh);
                }
            }
            gsync();
            /* phase B: GEMM update; block0 does tile(0,0) then factors next diag */
            {
                int g = (m + 127) / 128;
                if (blockIdx.x == 0) {
                    gemm_tile(k, m, 0, 0, &sh);
                    lu_diag(k + 64, &sh);
                } else {
                    for (int job = blockIdx.x; job < g * g; job += gridDim.x - 1)
                        gemm_tile(k, m, (job / g) * 128, (job % g) * 128, &sh);
                }
            }
            gsync();
        }

        /* ---- forward substitution (1 gsync per panel) ---- */
        if (blockIdx.x == 0) subst_diag_fwd(0, &sh);
        gsync();
        for (int k = 0; k + 64 < DIMP; k += 64) {
            __syncthreads();
            if (tid < 64) sh.sub.yc[tid] = d_y[k + tid];
            __syncthreads();
            if (blockIdx.x == 0) {
                for (int r = k + 64 + warp; r < k + 128; r += NWARPS)
                    subst_row_update(r, k, sh.sub.yc, lane);
                __syncthreads();
                subst_diag_fwd(k + 64, &sh);
            } else {
                int gw = (blockIdx.x - 1) * NWARPS + warp;
                int tot = (gridDim.x - 1) * NWARPS;
                for (int r = k + 128 + gw; r < DIMP; r += tot)
                    subst_row_update(r, k, sh.sub.yc, lane);
            }
            gsync();
        }

        /* ---- backward substitution (1 gsync per panel) ---- */
        if (blockIdx.x == 0) subst_diag_bwd(DIMP - 64, &sh);
        gsync();
        for (int k = DIMP - 64; k > 0; k -= 64) {
            __syncthreads();
            if (tid < 64) sh.sub.yc[tid] = d_y[k + tid];
            __syncthreads();
            if (blockIdx.x == 0) {
                for (int r = k - 64 + warp; r < k; r += NWARPS)
                    subst_row_update(r, k, sh.sub.yc, lane);
                __syncthreads();
                subst_diag_bwd(k - 64, &sh);
            } else {
                int gw = (blockIdx.x - 1) * NWARPS + warp;
                int tot = (gridDim.x - 1) * NWARPS;
                for (int r = gw; r < k - 64; r += tot)
                    subst_row_update(r, k, sh.sub.yc, lane);
            }
            gsync();
        }

        /* ---- Newton update ---- */
        for (int i = gtid; i < DIM; i += gsize) {
            float v = d_x[i] - d_y[i];
            if (i >= NB) v = fminf(fmaxf(v, 0.5f), 1.5f);
            d_x[i] = v;
        }
        gsync();
    }

    for (int i = gtid; i < DIM; i += gsize)
        P.out[i] = d_x[i];
}

extern "C" void kernel_launch(void* const* d_in, const int* in_sizes, int n_in,
                              void* d_out, int out_size)
{
    Params P;
    P.x_in   = (const float*)d_in[0];
    P.ei     = (const int*)  d_in[1];
    P.br_r   = (const float*)d_in[2];
    P.br_x   = (const float*)d_in[3];
    P.g_fr   = (const float*)d_in[4];
    P.b_fr   = (const float*)d_in[5];
    P.g_to   = (const float*)d_in[6];
    P.b_to   = (const float*)d_in[7];
    P.tap    = (const float*)d_in[8];
    P.shift  = (const float*)d_in[9];
    P.p_spec = (const float*)d_in[10];
    P.q_spec = (const float*)d_in[11];
    P.gs     = (const float*)d_in[12];
    P.bs     = (const float*)d_in[13];
    P.bt     = (const int*)  d_in[14];
    P.vmset  = (const float*)d_in[15];
    P.out    = (float*)d_out;

    int dev = 0, nsm = 0, per_sm = 0;
    cudaGetDevice(&dev);
    cudaDeviceGetAttribute(&nsm, cudaDevAttrMultiProcessorCount, dev);
    cudaOccupancyMaxActiveBlocksPerMultiprocessor(&per_sm, solver_kernel, NTHREADS, 0);
    if (per_sm < 1) per_sm = 1;
    int grid = nsm * per_sm;
    if (grid < 2) grid = 2;
    if (grid > 1024) grid = 1024;

    solver_kernel<<<grid, NTHREADS>>>(P);
}